// round 5
// baseline (speedup 1.0000x reference)
#include <cuda_runtime.h>
#include <cuda_bf16.h>
#include <cuda_fp16.h>
#include <math.h>
#include <stdint.h>

#define D_MODEL 256
#define D_FFN   1024
#define NHEADS  8
#define NLEV    4
#define NPTS    4
#define HDIM    32
#define BATCH   2
#define SLEN    21760
#define NTOK    (BATCH * SLEN)   // 43520

// ================= scratch (device globals; no allocation allowed) =================
__device__ __align__(16) __nv_bfloat16 g_src2b[NTOK * 512];   // [hi|lo]
__device__ __align__(16) __nv_bfloat16 g_q2[NTOK * 512];
__device__ __align__(16) __nv_bfloat16 g_samp2[NTOK * 512];
__device__ __align__(16) __nv_bfloat16 g_h22[NTOK * 512];
__device__ __align__(16) __nv_bfloat16 g_ffn2b[NTOK * 2048];

__device__ __align__(16) __half g_valueH[NTOK * D_MODEL];     // fp16 value
__device__ float g_off[NTOK * D_MODEL];
__device__ float g_attn[NTOK * NHEADS * 16];                  // raw logits (softmax fused in deform)
__device__ float g_src2[NTOK * D_MODEL];

// weights transposed [N][2K] = [hi | lo]
__device__ __align__(16) __nv_bfloat16 w2_v[256 * 512];
__device__ __align__(16) __nv_bfloat16 w2_qa[384 * 512];      // rows 0-255: W_off, 256-383: W_attn
__device__ __align__(16) __nv_bfloat16 w2_o[256 * 512];
__device__ __align__(16) __nv_bfloat16 w2_f1[1024 * 512];
__device__ __align__(16) __nv_bfloat16 w2_f2[256 * 2048];

// ================= helpers =================
__device__ __forceinline__ uint32_t smem_u32(const void* p) {
    uint32_t a;
    asm("{ .reg .u64 t; cvta.to.shared.u64 t, %1; cvt.u32.u64 %0, t; }" : "=r"(a) : "l"(p));
    return a;
}
__device__ __forceinline__ void ldm_x4(uint32_t* r, uint32_t addr) {
    asm volatile("ldmatrix.sync.aligned.m8n8.x4.shared.b16 {%0,%1,%2,%3}, [%4];"
                 : "=r"(r[0]), "=r"(r[1]), "=r"(r[2]), "=r"(r[3]) : "r"(addr));
}
__device__ __forceinline__ void mma16816(float* d, const uint32_t* a, const uint32_t* b) {
    asm volatile("mma.sync.aligned.m16n8k16.row.col.f32.bf16.bf16.f32 "
                 "{%0,%1,%2,%3}, {%4,%5,%6,%7}, {%8,%9}, {%0,%1,%2,%3};"
                 : "+f"(d[0]), "+f"(d[1]), "+f"(d[2]), "+f"(d[3])
                 : "r"(a[0]), "r"(a[1]), "r"(a[2]), "r"(a[3]), "r"(b[0]), "r"(b[1]));
}
__device__ __forceinline__ void cpa16(uint32_t dst, const void* src) {
    asm volatile("cp.async.cg.shared.global [%0], [%1], 16;" :: "r"(dst), "l"(src));
}
__device__ __forceinline__ void split2(float x, __nv_bfloat16& h, __nv_bfloat16& l) {
    h = __float2bfloat16(x);
    l = __float2bfloat16(x - __bfloat162float(h));
}

// ================= HMMA GEMM, bf16x3 terms from bf16x2 storage =================
// C[M,N] = epi( Ahi.Bhi + Ahi.Blo + Alo.Bhi + bias ), A/B stored [hi|lo] rowlen 2K0.
// CTA 128x128, 4 warps of 64x64, BK=64, 3-stage cp.async ring, 128 threads.
// EPI: 1 = gelu -> bf16x2 (rowlen 2N); 2 = bias + residual(aux), fp32;
//      3 = dual: col<256 -> C[.,256](bias), col>=256 -> Cb[.,128](aux bias); 4 = fp16 out.
static const int LDSB = 144;                  // 72 bf16 per smem row
static const int BUFB = 128 * LDSB;           // 18432 B
static const int GEMM_SMEM = 6 * BUFB;        // 110592 B (3 stages x A,B)

template <int EPI>
__global__ void __launch_bounds__(128, 2) mma_gemm(
    const __nv_bfloat16* __restrict__ A2, const __nv_bfloat16* __restrict__ B2,
    const float* __restrict__ bias, const float* __restrict__ aux,
    float* __restrict__ C, float* __restrict__ Cb,
    __nv_bfloat16* __restrict__ C3, __half* __restrict__ Ch,
    int N, int K0)
{
    extern __shared__ __align__(16) char sm[];
    const uint32_t smb = smem_u32(sm);
    const int tid = threadIdx.x;
    const int wid = tid >> 5, lane = tid & 31;
    const int wm = wid >> 1, wn = wid & 1;                // 2x2 warps of 64x64
    const int m0 = blockIdx.y * 128, n0 = blockIdx.x * 128;
    const int third = K0 >> 6;
    const int S = 3 * third;
    const int ldg = 2 * K0;

    float acc[4][8][4];
    #pragma unroll
    for (int i = 0; i < 4; i++)
        #pragma unroll
        for (int j = 0; j < 8; j++)
            #pragma unroll
            for (int r = 0; r < 4; r++) acc[i][j][r] = 0.f;

    auto prefetch = [&](int s) {
        int seg = (s >= 2 * third) ? 2 : ((s >= third) ? 1 : 0);
        int sk = (s - seg * third) << 6;
        int kA = ((seg == 2) ? K0 : 0) + sk;              // A: hi,hi,lo
        int kB = ((seg == 1) ? K0 : 0) + sk;              // B: hi,lo,hi
        const uint32_t ab = smb + (uint32_t)(s % 3) * (2u * BUFB);
        const uint32_t bb = ab + BUFB;
        #pragma unroll
        for (int i = 0; i < 16; i++) {
            int c = tid + (i << 7);                       // 0..2047
            int cc = c & 1023;
            int row = cc >> 3;
            int kc  = (cc & 7) << 3;
            uint32_t dst; const __nv_bfloat16* src;
            if (c < 1024) {
                dst = ab + (uint32_t)(row * LDSB + kc * 2);
                src = A2 + (size_t)(m0 + row) * ldg + kA + kc;
            } else {
                dst = bb + (uint32_t)(row * LDSB + kc * 2);
                src = B2 + (size_t)(n0 + row) * ldg + kB + kc;
            }
            cpa16(dst, src);
        }
        asm volatile("cp.async.commit_group;");
    };

    prefetch(0);
    if (S > 1) prefetch(1);

    for (int s = 0; s < S; s++) {
        if (s + 1 < S) asm volatile("cp.async.wait_group 1;");
        else           asm volatile("cp.async.wait_group 0;");
        __syncthreads();
        if (s + 2 < S) prefetch(s + 2);

        const uint32_t ab = smb + (uint32_t)(s % 3) * (2u * BUFB);
        const uint32_t bb = ab + BUFB;
        const uint32_t aoff = ab + (uint32_t)(((lane & 15) + wm * 64) * LDSB + ((lane >> 4) << 4));
        const uint32_t boff = bb + (uint32_t)((((lane & 7) + ((lane >> 4) << 3)) + wn * 64) * LDSB
                                              + (((lane >> 3) & 1) << 4));
        #pragma unroll
        for (int ks = 0; ks < 4; ks++) {
            const uint32_t kb = (uint32_t)(ks << 5);
            uint32_t afr[4][4], bfr[8][2];
            #pragma unroll
            for (int mi = 0; mi < 4; mi++)
                ldm_x4(afr[mi], aoff + (uint32_t)(mi * 16 * LDSB) + kb);
            #pragma unroll
            for (int nj = 0; nj < 4; nj++) {
                uint32_t r[4];
                ldm_x4(r, boff + (uint32_t)(nj * 16 * LDSB) + kb);
                bfr[nj * 2][0] = r[0]; bfr[nj * 2][1] = r[1];
                bfr[nj * 2 + 1][0] = r[2]; bfr[nj * 2 + 1][1] = r[3];
            }
            #pragma unroll
            for (int mi = 0; mi < 4; mi++)
                #pragma unroll
                for (int ni = 0; ni < 8; ni++)
                    mma16816(acc[mi][ni], afr[mi], bfr[ni]);
        }
    }
    __syncthreads();

    // ---- epilogue: stage 64x64 per warp in smem (stride 68 floats), store coalesced ----
    float* ws = (float*)sm + wid * (64 * 68);
    const int er = lane >> 2, ec = (lane & 3) * 2;
    #pragma unroll
    for (int mi = 0; mi < 4; mi++)
        #pragma unroll
        for (int ni = 0; ni < 8; ni++) {
            *(float2*)&ws[(mi * 16 + er) * 68 + ni * 8 + ec]     = make_float2(acc[mi][ni][0], acc[mi][ni][1]);
            *(float2*)&ws[(mi * 16 + er + 8) * 68 + ni * 8 + ec] = make_float2(acc[mi][ni][2], acc[mi][ni][3]);
        }
    __syncwarp();

    const int gc0 = n0 + wn * 64 + lane;
    const int gc1 = gc0 + 32;
    float b0, b1;
    if (EPI == 3) {
        b0 = (gc0 < 256) ? bias[gc0] : aux[gc0 - 256];
        b1 = (gc1 < 256) ? bias[gc1] : aux[gc1 - 256];
    } else { b0 = bias[gc0]; b1 = bias[gc1]; }

    for (int r = 0; r < 64; r++) {
        const int gr = m0 + wm * 64 + r;
        float v0 = ws[r * 68 + lane] + b0;
        float v1 = ws[r * 68 + 32 + lane] + b1;
        if (EPI == 1) {
            v0 = 0.5f * v0 * (1.0f + erff(v0 * 0.70710678118654752f));
            v1 = 0.5f * v1 * (1.0f + erff(v1 * 0.70710678118654752f));
            __nv_bfloat16 h, l;
            size_t base = (size_t)gr * (2 * (size_t)N);
            split2(v0, h, l); C3[base + gc0] = h; C3[base + N + gc0] = l;
            split2(v1, h, l); C3[base + gc1] = h; C3[base + N + gc1] = l;
        } else if (EPI == 2) {
            C[(size_t)gr * N + gc0] = v0 + aux[(size_t)gr * N + gc0];
            C[(size_t)gr * N + gc1] = v1 + aux[(size_t)gr * N + gc1];
        } else if (EPI == 3) {
            if (gc0 < 256) C[(size_t)gr * 256 + gc0] = v0;
            else           Cb[(size_t)gr * 128 + (gc0 - 256)] = v0;
            if (gc1 < 256) C[(size_t)gr * 256 + gc1] = v1;
            else           Cb[(size_t)gr * 128 + (gc1 - 256)] = v1;
        } else {  // EPI == 4
            Ch[(size_t)gr * N + gc0] = __float2half(v0);
            Ch[(size_t)gr * N + gc1] = __float2half(v1);
        }
    }
}

// ================= fused prep: src -> src2b split; q = LN1(src)+pos -> q2 split =================
__global__ void pre_kernel(const float* __restrict__ x,
                           const float* __restrict__ gamma,
                           const float* __restrict__ beta,
                           const float* __restrict__ pos) {
    int t = blockIdx.x;
    int c = threadIdx.x;
    float v = x[t * D_MODEL + c];
    {
        __nv_bfloat16 h, l; split2(v, h, l);
        size_t base = (size_t)t * 512;
        g_src2b[base + c] = h;
        g_src2b[base + 256 + c] = l;
    }
    float a = v, a2 = v * v;
    #pragma unroll
    for (int o = 16; o; o >>= 1) {
        a  += __shfl_xor_sync(0xffffffffu, a,  o);
        a2 += __shfl_xor_sync(0xffffffffu, a2, o);
    }
    __shared__ float s1[8], s2[8];
    if ((c & 31) == 0) { s1[c >> 5] = a; s2[c >> 5] = a2; }
    __syncthreads();
    float sum = 0.f, sq = 0.f;
    #pragma unroll
    for (int i = 0; i < 8; i++) { sum += s1[i]; sq += s2[i]; }
    float mu  = sum * (1.0f / D_MODEL);
    float var = sq * (1.0f / D_MODEL) - mu * mu;
    float rr  = rsqrtf(var + 1e-5f);
    float y   = (v - mu) * rr * gamma[c] + beta[c] + pos[t * D_MODEL + c];
    __nv_bfloat16 h, l; split2(y, h, l);
    size_t base = (size_t)t * 512;
    g_q2[base + c] = h;
    g_q2[base + 256 + c] = l;
}

// ================= layernorm2 -> bf16x2 =================
__global__ void ln2_kernel(const float* __restrict__ x,
                           const float* __restrict__ gamma,
                           const float* __restrict__ beta) {
    int t = blockIdx.x;
    int c = threadIdx.x;
    float v = x[t * D_MODEL + c];
    float a = v, a2 = v * v;
    #pragma unroll
    for (int o = 16; o; o >>= 1) {
        a  += __shfl_xor_sync(0xffffffffu, a,  o);
        a2 += __shfl_xor_sync(0xffffffffu, a2, o);
    }
    __shared__ float s1[8], s2[8];
    if ((c & 31) == 0) { s1[c >> 5] = a; s2[c >> 5] = a2; }
    __syncthreads();
    float sum = 0.f, sq = 0.f;
    #pragma unroll
    for (int i = 0; i < 8; i++) { sum += s1[i]; sq += s2[i]; }
    float mu  = sum * (1.0f / D_MODEL);
    float var = sq * (1.0f / D_MODEL) - mu * mu;
    float rr  = rsqrtf(var + 1e-5f);
    float y   = (v - mu) * rr * gamma[c] + beta[c];
    __nv_bfloat16 h, l; split2(y, h, l);
    size_t base = (size_t)t * 512;
    g_h22[base + c] = h;
    g_h22[base + 256 + c] = l;
}

// ================= one-shot weight prep =================
__global__ void wprep_all(const float* __restrict__ Wv, const float* __restrict__ Wo,
                          const float* __restrict__ Wa, const float* __restrict__ Wout,
                          const float* __restrict__ Wf1, const float* __restrict__ Wf2) {
    int i = blockIdx.x * blockDim.x + threadIdx.x;
    const float* W; __nv_bfloat16* B2; int K, N, rowOff, i2;
    if (i < 65536)        { W = Wv;  B2 = w2_v;  K = 256;  N = 256;  rowOff = 0;   i2 = i; }
    else if (i < 131072)  { W = Wo;  B2 = w2_qa; K = 256;  N = 256;  rowOff = 0;   i2 = i - 65536; }
    else if (i < 163840)  { W = Wa;  B2 = w2_qa; K = 256;  N = 128;  rowOff = 256; i2 = i - 131072; }
    else if (i < 229376)  { W = Wout;B2 = w2_o;  K = 256;  N = 256;  rowOff = 0;   i2 = i - 163840; }
    else if (i < 491520)  { W = Wf1; B2 = w2_f1; K = 256;  N = 1024; rowOff = 0;   i2 = i - 229376; }
    else if (i < 753664)  { W = Wf2; B2 = w2_f2; K = 1024; N = 256;  rowOff = 0;   i2 = i - 491520; }
    else return;
    int k = i2 / N, n = i2 - k * N;
    __nv_bfloat16 h, l; split2(W[i2], h, l);
    size_t base = (size_t)(n + rowOff) * (2 * (size_t)K);
    B2[base + k] = h;
    B2[base + K + k] = l;
}

// ================= deformable sampling + fused softmax -> bf16x2 =================
__global__ void deform_kernel(const float* __restrict__ ref) {
    const int lvH[4] = {128, 64, 32, 16};
    const int lvW[4] = {128, 64, 32, 16};
    const int lvS[4] = {0, 16384, 20480, 21504};

    int g = blockIdx.x * 8 + (threadIdx.x >> 5);
    int lane = threadIdx.x & 31;
    int b  = g / (SLEN * NHEADS);
    int rm = g - b * (SLEN * NHEADS);
    int qi = rm / NHEADS;
    int h  = rm - qi * NHEADS;
    int tok = b * SLEN + qi;

    // fused softmax over this head's 16 logits (lanes 0..15)
    float lg = (lane < 16) ? g_attn[(size_t)tok * 128 + h * 16 + lane] : -1e30f;
    float mx = lg;
    #pragma unroll
    for (int o = 8; o; o >>= 1) mx = fmaxf(mx, __shfl_xor_sync(0xffffffffu, mx, o));
    float e = (lane < 16) ? __expf(lg - mx) : 0.f;
    float se = e;
    #pragma unroll
    for (int o = 8; o; o >>= 1) se += __shfl_xor_sync(0xffffffffu, se, o);
    float wnorm = e / se;

    float acc = 0.f;
    #pragma unroll
    for (int lvl = 0; lvl < NLEV; lvl++) {
        const int Hh = lvH[lvl], Ww = lvW[lvl], st = lvS[lvl];
        float rx = ref[((size_t)tok * NLEV + lvl) * 2 + 0];
        float ry = ref[((size_t)tok * NLEV + lvl) * 2 + 1];
        #pragma unroll
        for (int p = 0; p < NPTS; p++) {
            const float* op = g_off + (size_t)tok * 256 + (((h * NLEV + lvl) * NPTS + p) * 2);
            float x = rx * (float)Ww + op[0] - 0.5f;
            float y = ry * (float)Hh + op[1] - 0.5f;
            float w = __shfl_sync(0xffffffffu, wnorm, lvl * 4 + p);

            float x0f = floorf(x), y0f = floorf(y);
            int x0 = (int)x0f, y0 = (int)y0f;
            float wx = x - x0f, wy = y - y0f;

            float v00 = 0.f, v01 = 0.f, v10 = 0.f, v11 = 0.f;
            int x1 = x0 + 1, y1 = y0 + 1;
            bool vx0 = (x0 >= 0) & (x0 < Ww);
            bool vx1 = (x1 >= 0) & (x1 < Ww);
            bool vy0 = (y0 >= 0) & (y0 < Hh);
            bool vy1 = (y1 >= 0) & (y1 < Hh);
            size_t rowBase = (size_t)(b * SLEN + st);
            if (vy0) {
                size_t rb = rowBase + (size_t)y0 * Ww;
                if (vx0) v00 = __half2float(g_valueH[((rb + x0) * NHEADS + h) * HDIM + lane]);
                if (vx1) v01 = __half2float(g_valueH[((rb + x1) * NHEADS + h) * HDIM + lane]);
            }
            if (vy1) {
                size_t rb = rowBase + (size_t)y1 * Ww;
                if (vx0) v10 = __half2float(g_valueH[((rb + x0) * NHEADS + h) * HDIM + lane]);
                if (vx1) v11 = __half2float(g_valueH[((rb + x1) * NHEADS + h) * HDIM + lane]);
            }
            float top = v00 + (v01 - v00) * wx;
            float bot = v10 + (v11 - v10) * wx;
            acc += w * (top + (bot - top) * wy);
        }
    }
    __nv_bfloat16 hh, ll; split2(acc, hh, ll);
    int c = h * HDIM + lane;
    size_t base = (size_t)tok * 512;
    g_samp2[base + c] = hh;
    g_samp2[base + 256 + c] = ll;
}

// ================= launch =================
extern "C" void kernel_launch(void* const* d_in, const int* in_sizes, int n_in,
                              void* d_out, int out_size) {
    const float* src  = (const float*)d_in[0];
    const float* pos  = (const float*)d_in[1];
    const float* refp = (const float*)d_in[2];
    const float* n1g = (const float*)d_in[5];
    const float* n1b = (const float*)d_in[6];
    const float* n2g = (const float*)d_in[7];
    const float* n2b = (const float*)d_in[8];
    const float* Wv  = (const float*)d_in[9];
    const float* bv  = (const float*)d_in[10];
    const float* Wo  = (const float*)d_in[11];
    const float* bo  = (const float*)d_in[12];
    const float* Wa  = (const float*)d_in[13];
    const float* ba  = (const float*)d_in[14];
    const float* Wout= (const float*)d_in[15];
    const float* bout= (const float*)d_in[16];
    const float* Wf1 = (const float*)d_in[17];
    const float* bf1 = (const float*)d_in[18];
    const float* Wf2 = (const float*)d_in[19];
    const float* bf2 = (const float*)d_in[20];
    float* out = (float*)d_out;

    __nv_bfloat16 *src2b, *q2, *samp2, *h22, *ffn2b;
    __nv_bfloat16 *wv2, *wqa2, *wo2, *wf12, *wf22;
    __half* pValH;
    float *pOff, *pAttn, *pSrc2;
    cudaGetSymbolAddress((void**)&src2b, g_src2b);
    cudaGetSymbolAddress((void**)&q2,    g_q2);
    cudaGetSymbolAddress((void**)&samp2, g_samp2);
    cudaGetSymbolAddress((void**)&h22,   g_h22);
    cudaGetSymbolAddress((void**)&ffn2b, g_ffn2b);
    cudaGetSymbolAddress((void**)&wv2,   w2_v);
    cudaGetSymbolAddress((void**)&wqa2,  w2_qa);
    cudaGetSymbolAddress((void**)&wo2,   w2_o);
    cudaGetSymbolAddress((void**)&wf12,  w2_f1);
    cudaGetSymbolAddress((void**)&wf22,  w2_f2);
    cudaGetSymbolAddress((void**)&pValH, g_valueH);
    cudaGetSymbolAddress((void**)&pOff,  g_off);
    cudaGetSymbolAddress((void**)&pAttn, g_attn);
    cudaGetSymbolAddress((void**)&pSrc2, g_src2);

    cudaFuncSetAttribute(mma_gemm<1>, cudaFuncAttributeMaxDynamicSharedMemorySize, GEMM_SMEM);
    cudaFuncSetAttribute(mma_gemm<2>, cudaFuncAttributeMaxDynamicSharedMemorySize, GEMM_SMEM);
    cudaFuncSetAttribute(mma_gemm<3>, cudaFuncAttributeMaxDynamicSharedMemorySize, GEMM_SMEM);
    cudaFuncSetAttribute(mma_gemm<4>, cudaFuncAttributeMaxDynamicSharedMemorySize, GEMM_SMEM);

    dim3 t256(256), t128(128);
    const int MB = NTOK / 128;   // 340

    wprep_all<<<(753664 + 255) / 256, t256>>>(Wv, Wo, Wa, Wout, Wf1, Wf2);         // 0
    pre_kernel<<<NTOK, t256>>>(src, n1g, n1b, pos);                                // 1
    mma_gemm<4><<<dim3(2, MB), t128, GEMM_SMEM>>>(src2b, wv2, bv, nullptr,         // 2: value (fp16)
                                                  nullptr, nullptr, nullptr, pValH, 256, 256);
    mma_gemm<3><<<dim3(3, MB), t128, GEMM_SMEM>>>(q2, wqa2, bo, ba,                // 3: offsets+logits
                                                  pOff, pAttn, nullptr, nullptr, 384, 256);
    deform_kernel<<<(NTOK * NHEADS) / 8, t256>>>(refp);                            // 4
    mma_gemm<2><<<dim3(2, MB), t128, GEMM_SMEM>>>(samp2, wo2, bout, src,           // 5: out-proj + res
                                                  pSrc2, nullptr, nullptr, nullptr, 256, 256);
    ln2_kernel<<<NTOK, t256>>>(pSrc2, n2g, n2b);                                   // 6
    mma_gemm<1><<<dim3(8, MB), t128, GEMM_SMEM>>>(h22, wf12, bf1, nullptr,         // 7: FFN1 + gelu
                                                  nullptr, nullptr, ffn2b, nullptr, 1024, 256);
    mma_gemm<2><<<dim3(2, MB), t128, GEMM_SMEM>>>(ffn2b, wf22, bf2, pSrc2,         // 8: FFN2 + res
                                                  out, nullptr, nullptr, nullptr, 256, 1024);
}

// round 6
// speedup vs baseline: 1.7415x; 1.7415x over previous
#include <cuda_runtime.h>
#include <cuda_fp16.h>
#include <math.h>
#include <stdint.h>

#define D_MODEL 256
#define D_FFN   1024
#define NHEADS  8
#define NLEV    4
#define NPTS    4
#define HDIM    32
#define BATCH   2
#define SLEN    21760
#define NTOK    (BATCH * SLEN)   // 43520

// ================= scratch (device globals; no allocation allowed) =================
__device__ __align__(16) __half g_srcH[NTOK * D_MODEL];
__device__ __align__(16) __half g_qH[NTOK * D_MODEL];
__device__ __align__(16) __half g_sampH[NTOK * D_MODEL];
__device__ __align__(16) __half g_h2H[NTOK * D_MODEL];
__device__ __align__(16) __half g_ffnH[NTOK * D_FFN];
__device__ __align__(16) __half g_valueH[NTOK * D_MODEL];     // planar: [h][tok][dim]

__device__ float g_off[NTOK * D_MODEL];
__device__ float g_attn[NTOK * NHEADS * 16];                  // raw logits (softmax fused in deform)
__device__ float g_src2[NTOK * D_MODEL];

// weights transposed [N][K], fp16
__device__ __align__(16) __half w_v[256 * 256];
__device__ __align__(16) __half w_qa[384 * 256];              // rows 0-255: W_off, 256-383: W_attn
__device__ __align__(16) __half w_o[256 * 256];
__device__ __align__(16) __half w_f1[1024 * 256];
__device__ __align__(16) __half w_f2[256 * 1024];

// ================= helpers =================
__device__ __forceinline__ uint32_t smem_u32(const void* p) {
    uint32_t a;
    asm("{ .reg .u64 t; cvta.to.shared.u64 t, %1; cvt.u32.u64 %0, t; }" : "=r"(a) : "l"(p));
    return a;
}
__device__ __forceinline__ void ldm_x4(uint32_t* r, uint32_t addr) {
    asm volatile("ldmatrix.sync.aligned.m8n8.x4.shared.b16 {%0,%1,%2,%3}, [%4];"
                 : "=r"(r[0]), "=r"(r[1]), "=r"(r[2]), "=r"(r[3]) : "r"(addr));
}
__device__ __forceinline__ void mma16816(float* d, const uint32_t* a, const uint32_t* b) {
    asm volatile("mma.sync.aligned.m16n8k16.row.col.f32.f16.f16.f32 "
                 "{%0,%1,%2,%3}, {%4,%5,%6,%7}, {%8,%9}, {%0,%1,%2,%3};"
                 : "+f"(d[0]), "+f"(d[1]), "+f"(d[2]), "+f"(d[3])
                 : "r"(a[0]), "r"(a[1]), "r"(a[2]), "r"(a[3]), "r"(b[0]), "r"(b[1]));
}
__device__ __forceinline__ void cpa16(uint32_t dst, const void* src) {
    asm volatile("cp.async.cg.shared.global [%0], [%1], 16;" :: "r"(dst), "l"(src));
}

// ================= fp16 HMMA GEMM: C[M,N] = epi(A[M,K] @ (B[N,K])^T + bias) =================
// CTA 128x128, 4 warps of 64x64, BK=64, 3-stage cp.async ring, 128 threads.
// EPI: 1 = gelu(x+bias) -> fp16 [tok][N]; 2 = x+bias+aux(residual) -> fp32;
//      3 = dual: col<256 -> C[.,256](bias), col>=256 -> Cb[.,128](aux bias);
//      4 = fp16 planar value out: Ch[(h*NTOK+row)*32 + d]
static const int LDSB = 144;                  // 64 fp16 (128 B) + 16 B pad
static const int BUFB = 128 * LDSB;           // 18432 B
static const int GEMM_SMEM = 6 * BUFB;        // 110592 B (3 stages x A,B)

template <int EPI>
__global__ void __launch_bounds__(128, 2) mma_gemm(
    const __half* __restrict__ A, const __half* __restrict__ B,
    const float* __restrict__ bias, const float* __restrict__ aux,
    float* __restrict__ C, float* __restrict__ Cb, __half* __restrict__ Ch,
    int N, int K)
{
    extern __shared__ __align__(16) char sm[];
    const uint32_t smb = smem_u32(sm);
    const int tid = threadIdx.x;
    const int wid = tid >> 5, lane = tid & 31;
    const int wm = wid >> 1, wn = wid & 1;                // 2x2 warps of 64x64
    const int m0 = blockIdx.y * 128, n0 = blockIdx.x * 128;
    const int S = K >> 6;

    float acc[4][8][4];
    #pragma unroll
    for (int i = 0; i < 4; i++)
        #pragma unroll
        for (int j = 0; j < 8; j++)
            #pragma unroll
            for (int r = 0; r < 4; r++) acc[i][j][r] = 0.f;

    auto prefetch = [&](int s) {
        int k0 = s << 6;
        const uint32_t ab = smb + (uint32_t)(s % 3) * (2u * BUFB);
        const uint32_t bb = ab + BUFB;
        #pragma unroll
        for (int i = 0; i < 16; i++) {
            int c = tid + (i << 7);                       // 0..2047
            int cc = c & 1023;
            int row = cc >> 3;
            int kc  = (cc & 7) << 3;                      // fp16 elems, 16B chunks
            uint32_t dst; const __half* src;
            if (c < 1024) {
                dst = ab + (uint32_t)(row * LDSB + kc * 2);
                src = A + (size_t)(m0 + row) * K + k0 + kc;
            } else {
                dst = bb + (uint32_t)(row * LDSB + kc * 2);
                src = B + (size_t)(n0 + row) * K + k0 + kc;
            }
            cpa16(dst, src);
        }
        asm volatile("cp.async.commit_group;");
    };

    prefetch(0);
    if (S > 1) prefetch(1);

    for (int s = 0; s < S; s++) {
        if (s + 1 < S) asm volatile("cp.async.wait_group 1;");
        else           asm volatile("cp.async.wait_group 0;");
        __syncthreads();
        if (s + 2 < S) prefetch(s + 2);

        const uint32_t ab = smb + (uint32_t)(s % 3) * (2u * BUFB);
        const uint32_t bb = ab + BUFB;
        const uint32_t aoff = ab + (uint32_t)(((lane & 15) + wm * 64) * LDSB + ((lane >> 4) << 4));
        const uint32_t boff = bb + (uint32_t)((((lane & 7) + ((lane >> 4) << 3)) + wn * 64) * LDSB
                                              + (((lane >> 3) & 1) << 4));
        #pragma unroll
        for (int ks = 0; ks < 4; ks++) {
            const uint32_t kb = (uint32_t)(ks << 5);
            uint32_t afr[4][4], bfr[8][2];
            #pragma unroll
            for (int mi = 0; mi < 4; mi++)
                ldm_x4(afr[mi], aoff + (uint32_t)(mi * 16 * LDSB) + kb);
            #pragma unroll
            for (int nj = 0; nj < 4; nj++) {
                uint32_t r[4];
                ldm_x4(r, boff + (uint32_t)(nj * 16 * LDSB) + kb);
                bfr[nj * 2][0] = r[0]; bfr[nj * 2][1] = r[1];
                bfr[nj * 2 + 1][0] = r[2]; bfr[nj * 2 + 1][1] = r[3];
            }
            #pragma unroll
            for (int mi = 0; mi < 4; mi++)
                #pragma unroll
                for (int ni = 0; ni < 8; ni++)
                    mma16816(acc[mi][ni], afr[mi], bfr[ni]);
        }
    }
    __syncthreads();

    // ---- epilogue: stage 64x64 per warp in smem (stride 68 floats), store coalesced ----
    float* ws = (float*)sm + wid * (64 * 68);
    const int er = lane >> 2, ec = (lane & 3) * 2;
    #pragma unroll
    for (int mi = 0; mi < 4; mi++)
        #pragma unroll
        for (int ni = 0; ni < 8; ni++) {
            *(float2*)&ws[(mi * 16 + er) * 68 + ni * 8 + ec]     = make_float2(acc[mi][ni][0], acc[mi][ni][1]);
            *(float2*)&ws[(mi * 16 + er + 8) * 68 + ni * 8 + ec] = make_float2(acc[mi][ni][2], acc[mi][ni][3]);
        }
    __syncwarp();

    const int gc0 = n0 + wn * 64 + lane;
    const int gc1 = gc0 + 32;
    float b0, b1;
    if (EPI == 3) {
        b0 = (gc0 < 256) ? bias[gc0] : aux[gc0 - 256];
        b1 = (gc1 < 256) ? bias[gc1] : aux[gc1 - 256];
    } else { b0 = bias[gc0]; b1 = bias[gc1]; }

    for (int r = 0; r < 64; r++) {
        const int gr = m0 + wm * 64 + r;
        float v0 = ws[r * 68 + lane] + b0;
        float v1 = ws[r * 68 + 32 + lane] + b1;
        if (EPI == 1) {
            v0 = 0.5f * v0 * (1.0f + erff(v0 * 0.70710678118654752f));
            v1 = 0.5f * v1 * (1.0f + erff(v1 * 0.70710678118654752f));
            Ch[(size_t)gr * N + gc0] = __float2half(v0);
            Ch[(size_t)gr * N + gc1] = __float2half(v1);
        } else if (EPI == 2) {
            C[(size_t)gr * N + gc0] = v0 + aux[(size_t)gr * N + gc0];
            C[(size_t)gr * N + gc1] = v1 + aux[(size_t)gr * N + gc1];
        } else if (EPI == 3) {
            if (gc0 < 256) C[(size_t)gr * 256 + gc0] = v0;
            else           Cb[(size_t)gr * 128 + (gc0 - 256)] = v0;
            if (gc1 < 256) C[(size_t)gr * 256 + gc1] = v1;
            else           Cb[(size_t)gr * 128 + (gc1 - 256)] = v1;
        } else {  // EPI == 4: planar value
            Ch[((size_t)(gc0 >> 5) * NTOK + gr) * 32 + (gc0 & 31)] = __float2half(v0);
            Ch[((size_t)(gc1 >> 5) * NTOK + gr) * 32 + (gc1 & 31)] = __float2half(v1);
        }
    }
}

// ================= fused prep: src -> fp16; q = LN1(src)+pos -> fp16 =================
__global__ void pre_kernel(const float* __restrict__ x,
                           const float* __restrict__ gamma,
                           const float* __restrict__ beta,
                           const float* __restrict__ pos) {
    int t = blockIdx.x;
    int c = threadIdx.x;
    float v = x[t * D_MODEL + c];
    g_srcH[(size_t)t * D_MODEL + c] = __float2half(v);
    float a = v, a2 = v * v;
    #pragma unroll
    for (int o = 16; o; o >>= 1) {
        a  += __shfl_xor_sync(0xffffffffu, a,  o);
        a2 += __shfl_xor_sync(0xffffffffu, a2, o);
    }
    __shared__ float s1[8], s2[8];
    if ((c & 31) == 0) { s1[c >> 5] = a; s2[c >> 5] = a2; }
    __syncthreads();
    float sum = 0.f, sq = 0.f;
    #pragma unroll
    for (int i = 0; i < 8; i++) { sum += s1[i]; sq += s2[i]; }
    float mu  = sum * (1.0f / D_MODEL);
    float var = sq * (1.0f / D_MODEL) - mu * mu;
    float rr  = rsqrtf(var + 1e-5f);
    float y   = (v - mu) * rr * gamma[c] + beta[c] + pos[t * D_MODEL + c];
    g_qH[(size_t)t * D_MODEL + c] = __float2half(y);
}

// ================= layernorm2 -> fp16 =================
__global__ void ln2_kernel(const float* __restrict__ x,
                           const float* __restrict__ gamma,
                           const float* __restrict__ beta) {
    int t = blockIdx.x;
    int c = threadIdx.x;
    float v = x[t * D_MODEL + c];
    float a = v, a2 = v * v;
    #pragma unroll
    for (int o = 16; o; o >>= 1) {
        a  += __shfl_xor_sync(0xffffffffu, a,  o);
        a2 += __shfl_xor_sync(0xffffffffu, a2, o);
    }
    __shared__ float s1[8], s2[8];
    if ((c & 31) == 0) { s1[c >> 5] = a; s2[c >> 5] = a2; }
    __syncthreads();
    float sum = 0.f, sq = 0.f;
    #pragma unroll
    for (int i = 0; i < 8; i++) { sum += s1[i]; sq += s2[i]; }
    float mu  = sum * (1.0f / D_MODEL);
    float var = sq * (1.0f / D_MODEL) - mu * mu;
    float rr  = rsqrtf(var + 1e-5f);
    float y   = (v - mu) * rr * gamma[c] + beta[c];
    g_h2H[(size_t)t * D_MODEL + c] = __float2half(y);
}

// ================= one-shot weight prep: W[K,N] -> fp16 [N][K] =================
__global__ void wprep_all(const float* __restrict__ Wv, const float* __restrict__ Wo,
                          const float* __restrict__ Wa, const float* __restrict__ Wout,
                          const float* __restrict__ Wf1, const float* __restrict__ Wf2) {
    int i = blockIdx.x * blockDim.x + threadIdx.x;
    const float* W; __half* B; int K, N, rowOff, i2;
    if (i < 65536)        { W = Wv;  B = w_v;  K = 256;  N = 256;  rowOff = 0;   i2 = i; }
    else if (i < 131072)  { W = Wo;  B = w_qa; K = 256;  N = 256;  rowOff = 0;   i2 = i - 65536; }
    else if (i < 163840)  { W = Wa;  B = w_qa; K = 256;  N = 128;  rowOff = 256; i2 = i - 131072; }
    else if (i < 229376)  { W = Wout;B = w_o;  K = 256;  N = 256;  rowOff = 0;   i2 = i - 163840; }
    else if (i < 491520)  { W = Wf1; B = w_f1; K = 256;  N = 1024; rowOff = 0;   i2 = i - 229376; }
    else if (i < 753664)  { W = Wf2; B = w_f2; K = 1024; N = 256;  rowOff = 0;   i2 = i - 491520; }
    else return;
    int k = i2 / N, n = i2 - k * N;
    B[(size_t)(n + rowOff) * K + k] = __float2half(W[i2]);
}

// ================= deform: softmax fused, 2 points per warp (half-warp each), half2 loads =================
__global__ void deform_kernel(const float* __restrict__ ref) {
    const int lvH[4] = {128, 64, 32, 16};
    const int lvW[4] = {128, 64, 32, 16};
    const int lvS[4] = {0, 16384, 20480, 21504};

    int g = blockIdx.x * 8 + (threadIdx.x >> 5);
    int lane = threadIdx.x & 31;
    int b  = g / (SLEN * NHEADS);
    int rm = g - b * (SLEN * NHEADS);
    int qi = rm / NHEADS;
    int h  = rm - qi * NHEADS;
    int tok = b * SLEN + qi;

    // softmax over 16 logits (lanes 0..15 carry them; xor offsets stay within group)
    float lg = (lane < 16) ? g_attn[(size_t)tok * 128 + h * 16 + lane] : -1e30f;
    float mx = lg;
    #pragma unroll
    for (int o = 8; o; o >>= 1) mx = fmaxf(mx, __shfl_xor_sync(0xffffffffu, mx, o));
    float e = (lane < 16) ? __expf(lg - mx) : 0.f;
    float se = e;
    #pragma unroll
    for (int o = 8; o; o >>= 1) se += __shfl_xor_sync(0xffffffffu, se, o);
    float wnorm = e / se;

    const int half = lane >> 4;        // which point of the pair
    const int li   = lane & 15;        // dim pair index: dims (2li, 2li+1)

    float2 acc = make_float2(0.f, 0.f);
    #pragma unroll
    for (int lvl = 0; lvl < NLEV; lvl++) {
        const int Hh = lvH[lvl], Ww = lvW[lvl], st = lvS[lvl];
        float rx = ref[((size_t)tok * NLEV + lvl) * 2 + 0];
        float ry = ref[((size_t)tok * NLEV + lvl) * 2 + 1];
        #pragma unroll
        for (int ps = 0; ps < NPTS; ps += 2) {
            const int p = ps + half;
            const float* op = g_off + (size_t)tok * 256 + (((h * NLEV + lvl) * NPTS + p) * 2);
            float x = rx * (float)Ww + op[0] - 0.5f;
            float y = ry * (float)Hh + op[1] - 0.5f;
            float w = __shfl_sync(0xffffffffu, wnorm, lvl * 4 + p);

            float x0f = floorf(x), y0f = floorf(y);
            int x0 = (int)x0f, y0 = (int)y0f;
            float wx = x - x0f, wy = y - y0f;
            int x1 = x0 + 1, y1 = y0 + 1;
            bool vx0 = (x0 >= 0) & (x0 < Ww);
            bool vx1 = (x1 >= 0) & (x1 < Ww);
            bool vy0 = (y0 >= 0) & (y0 < Hh);
            bool vy1 = (y1 >= 0) & (y1 < Hh);

            const size_t pb = (size_t)h * NTOK + (size_t)(b * SLEN + st);
            float2 v00 = make_float2(0.f, 0.f), v01 = v00, v10 = v00, v11 = v00;
            if (vy0) {
                size_t rb = pb + (size_t)y0 * Ww;
                if (vx0) v00 = __half22float2(*(const __half2*)&g_valueH[(rb + x0) * 32 + li * 2]);
                if (vx1) v01 = __half22float2(*(const __half2*)&g_valueH[(rb + x1) * 32 + li * 2]);
            }
            if (vy1) {
                size_t rb = pb + (size_t)y1 * Ww;
                if (vx0) v10 = __half22float2(*(const __half2*)&g_valueH[(rb + x0) * 32 + li * 2]);
                if (vx1) v11 = __half22float2(*(const __half2*)&g_valueH[(rb + x1) * 32 + li * 2]);
            }
            float tx0 = v00.x + (v01.x - v00.x) * wx;
            float tx1 = v10.x + (v11.x - v10.x) * wx;
            float ty0 = v00.y + (v01.y - v00.y) * wx;
            float ty1 = v10.y + (v11.y - v10.y) * wx;
            acc.x += w * (tx0 + (tx1 - tx0) * wy);
            acc.y += w * (ty0 + (ty1 - ty0) * wy);
        }
    }
    // combine the two half-warps (points p and p+1)
    acc.x += __shfl_xor_sync(0xffffffffu, acc.x, 16);
    acc.y += __shfl_xor_sync(0xffffffffu, acc.y, 16);
    if (lane < 16) {
        __half2 hv = __floats2half2_rn(acc.x, acc.y);
        *(__half2*)&g_sampH[(size_t)tok * D_MODEL + h * HDIM + li * 2] = hv;
    }
}

// ================= launch =================
extern "C" void kernel_launch(void* const* d_in, const int* in_sizes, int n_in,
                              void* d_out, int out_size) {
    const float* src  = (const float*)d_in[0];
    const float* pos  = (const float*)d_in[1];
    const float* refp = (const float*)d_in[2];
    const float* n1g = (const float*)d_in[5];
    const float* n1b = (const float*)d_in[6];
    const float* n2g = (const float*)d_in[7];
    const float* n2b = (const float*)d_in[8];
    const float* Wv  = (const float*)d_in[9];
    const float* bv  = (const float*)d_in[10];
    const float* Wo  = (const float*)d_in[11];
    const float* bo  = (const float*)d_in[12];
    const float* Wa  = (const float*)d_in[13];
    const float* ba  = (const float*)d_in[14];
    const float* Wout= (const float*)d_in[15];
    const float* bout= (const float*)d_in[16];
    const float* Wf1 = (const float*)d_in[17];
    const float* bf1 = (const float*)d_in[18];
    const float* Wf2 = (const float*)d_in[19];
    const float* bf2 = (const float*)d_in[20];
    float* out = (float*)d_out;

    __half *srcH, *qH, *sampH, *h2H, *ffnH, *valH;
    __half *wv, *wqa, *wo, *wf1, *wf2;
    float *pOff, *pAttn, *pSrc2;
    cudaGetSymbolAddress((void**)&srcH, g_srcH);
    cudaGetSymbolAddress((void**)&qH,   g_qH);
    cudaGetSymbolAddress((void**)&sampH,g_sampH);
    cudaGetSymbolAddress((void**)&h2H,  g_h2H);
    cudaGetSymbolAddress((void**)&ffnH, g_ffnH);
    cudaGetSymbolAddress((void**)&valH, g_valueH);
    cudaGetSymbolAddress((void**)&wv,   w_v);
    cudaGetSymbolAddress((void**)&wqa,  w_qa);
    cudaGetSymbolAddress((void**)&wo,   w_o);
    cudaGetSymbolAddress((void**)&wf1,  w_f1);
    cudaGetSymbolAddress((void**)&wf2,  w_f2);
    cudaGetSymbolAddress((void**)&pOff,  g_off);
    cudaGetSymbolAddress((void**)&pAttn, g_attn);
    cudaGetSymbolAddress((void**)&pSrc2, g_src2);

    cudaFuncSetAttribute(mma_gemm<1>, cudaFuncAttributeMaxDynamicSharedMemorySize, GEMM_SMEM);
    cudaFuncSetAttribute(mma_gemm<2>, cudaFuncAttributeMaxDynamicSharedMemorySize, GEMM_SMEM);
    cudaFuncSetAttribute(mma_gemm<3>, cudaFuncAttributeMaxDynamicSharedMemorySize, GEMM_SMEM);
    cudaFuncSetAttribute(mma_gemm<4>, cudaFuncAttributeMaxDynamicSharedMemorySize, GEMM_SMEM);

    dim3 t256(256), t128(128);
    const int MB = NTOK / 128;   // 340

    wprep_all<<<(753664 + 255) / 256, t256>>>(Wv, Wo, Wa, Wout, Wf1, Wf2);          // 0
    pre_kernel<<<NTOK, t256>>>(src, n1g, n1b, pos);                                 // 1
    mma_gemm<4><<<dim3(2, MB), t128, GEMM_SMEM>>>(srcH, wv, bv, nullptr,            // 2: value (planar fp16)
                                                  nullptr, nullptr, valH, 256, 256);
    mma_gemm<3><<<dim3(3, MB), t128, GEMM_SMEM>>>(qH, wqa, bo, ba,                  // 3: offsets+logits
                                                  pOff, pAttn, nullptr, 384, 256);
    deform_kernel<<<(NTOK * NHEADS) / 8, t256>>>(refp);                             // 4
    mma_gemm<2><<<dim3(2, MB), t128, GEMM_SMEM>>>(sampH, wo, bout, src,             // 5: out-proj + residual
                                                  pSrc2, nullptr, nullptr, 256, 256);
    ln2_kernel<<<NTOK, t256>>>(pSrc2, n2g, n2b);                                    // 6
    mma_gemm<1><<<dim3(8, MB), t128, GEMM_SMEM>>>(h2H, wf1, bf1, nullptr,           // 7: FFN1 + gelu
                                                  nullptr, nullptr, ffnH, 1024, 256);
    mma_gemm<2><<<dim3(2, MB), t128, GEMM_SMEM>>>(ffnH, wf2, bf2, pSrc2,            // 8: FFN2 + residual
                                                  out, nullptr, nullptr, 256, 1024);
}